// round 3
// baseline (speedup 1.0000x reference)
#include <cuda_runtime.h>
#include <cuda_bf16.h>
typedef unsigned int u32;

#define NT1 128
#define ED  256
#define HD  512
#define G4  2048
#define RTOT 2176
#define NCT 500

__device__ float d_xT[ED*NT1];
__device__ float d_xg[2*NT1*G4];
__device__ float d_hbuf[2*2*HD];
__device__ float d_hcat[NT1*2*HD];
__device__ float d_u[NT1*HD];
__device__ float d_s[NT1*HD];
__device__ float d_z[(size_t)RTOT*HD];
__device__ float d_pm[(size_t)RTOT*NCT];
__device__ float d_ps[(size_t)RTOT*NCT];
__device__ float d_tgt[RTOT];
__device__ u32 d_keys[4];
__device__ int d_barc[2];
__device__ float d_kl, d_acc;

__device__ __forceinline__ uint2 tf2x32(u32 k0,u32 k1,u32 c0,u32 c1){
    u32 ks2=0x1BD11BDAu^k0^k1, x0=c0+k0, x1=c1+k1;
#define TFR(r) {x0+=x1; x1=__funnelshift_l(x1,x1,r); x1^=x0;}
    TFR(13)TFR(15)TFR(26)TFR(6)  x0+=k1;  x1+=ks2+1u;
    TFR(17)TFR(29)TFR(16)TFR(24) x0+=ks2; x1+=k0+2u;
    TFR(13)TFR(15)TFR(26)TFR(6)  x0+=k0;  x1+=k1+3u;
    TFR(17)TFR(29)TFR(16)TFR(24) x0+=k1;  x1+=ks2+4u;
    TFR(13)TFR(15)TFR(26)TFR(6)  x0+=ks2; x1+=k0+5u;
#undef TFR
    return make_uint2(x0,x1);
}
__device__ __forceinline__ float jnormal(u32 bits){
    float f=__uint_as_float((bits>>9)|0x3f800000u)-1.0f;
    const float lo=__int_as_float(0xBF7FFFFF);
    float u=fmaxf(lo, f*(1.0f-lo)+lo);
    float w=-log1pf(-u*u), p;
    if(w<5.0f){ w-=2.5f;
        p=2.81022636e-08f;           p=fmaf(p,w,3.43273939e-07f);
        p=fmaf(p,w,-3.5233877e-06f); p=fmaf(p,w,-4.39150654e-06f);
        p=fmaf(p,w,0.00021858087f);  p=fmaf(p,w,-0.00125372503f);
        p=fmaf(p,w,-0.00417768164f); p=fmaf(p,w,0.246640727f);
        p=fmaf(p,w,1.50140941f);
    } else { w=sqrtf(w)-3.0f;
        p=-0.000200214257f;          p=fmaf(p,w,0.000100950558f);
        p=fmaf(p,w,0.00134934322f);  p=fmaf(p,w,-0.00367342844f);
        p=fmaf(p,w,0.00573950773f);  p=fmaf(p,w,-0.0076224613f);
        p=fmaf(p,w,0.00943887047f);  p=fmaf(p,w,1.00167406f);
        p=fmaf(p,w,2.83297682f);
    }
    return 1.41421354f*(p*u);
}
__device__ __forceinline__ float sigf(float x){ return 1.0f/(1.0f+expf(-x)); }

__global__ void k_init(const int* __restrict__ wl1, const float* __restrict__ emb){
    int tid=blockIdx.x*blockDim.x+threadIdx.x;
    int t=tid&127, k=tid>>7;
    d_xT[k*NT1+t]=emb[(size_t)wl1[t]*ED+k];
    if(tid<2048) d_hbuf[tid]=0.0f;
    if(tid<2) d_barc[tid]=0;
    if(tid==0){
        d_kl=0.0f; d_acc=0.0f;
        uint2 a=tf2x32(0u,42u,0u,0u), b=tf2x32(0u,42u,0u,1u);
        d_keys[0]=a.x; d_keys[1]=a.y; d_keys[2]=b.x; d_keys[3]=b.y;
    }
}

__global__ void k_xg(const float* __restrict__ Wf,const float* __restrict__ bif,
                     const float* __restrict__ bhf,const float* __restrict__ Wb,
                     const float* __restrict__ bib,const float* __restrict__ bhb){
    int dir=blockIdx.y, j0=blockIdx.x*16, t=threadIdx.x;
    const float* W = dir?Wb:Wf; const float* b1=dir?bib:bif; const float* b2=dir?bhb:bhf;
    __shared__ float Ws[16][ED]; __shared__ float bs[16];
    for(int i=t;i<16*ED;i+=128) Ws[i>>8][i&255]=W[(size_t)(j0+(i>>8))*ED+(i&255)];
    if(t<16) bs[t]=b1[j0+t]+b2[j0+t];
    __syncthreads();
    int ts = dir?(127-t):t;
    float acc[16];
#pragma unroll
    for(int c=0;c<16;c++) acc[c]=0.0f;
    for(int k=0;k<ED;k++){
        float xv=d_xT[k*NT1+ts];
#pragma unroll
        for(int c=0;c<16;c++) acc[c]=fmaf(xv,Ws[c][k],acc[c]);
    }
#pragma unroll
    for(int c=0;c<16;c++) d_xg[(size_t)(dir*NT1+t)*G4+j0+c]=acc[c]+bs[c];
}

__global__ void __launch_bounds__(256,1) k_lstm(const float* __restrict__ Whf,
                                                const float* __restrict__ Whb){
    int bid=blockIdx.x, dir=bid>>6, blk=bid&63, j0=blk*8;
    int tid=threadIdx.x, wp=tid>>5, l=tid&31, g=l>>3, seg=l&7;
    int j=j0+wp;
    const float* Whh = dir?Whb:Whf;
    float w[64];
    {
        const float* wr=Whh+(size_t)(g*HD+j)*HD+seg;
#pragma unroll
        for(int ii=0;ii<64;ii++) w[ii]=wr[ii*8];
    }
    __shared__ float hs[HD];
    float c=0.0f;
    volatile int* bar=&d_barc[dir];
    for(int s=0;s<NT1;s++){
        int rb=s&1, base=(dir*2+rb)*HD;
        hs[tid]    =__ldcg(&d_hbuf[base+tid]);
        hs[tid+256]=__ldcg(&d_hbuf[base+tid+256]);
        __syncthreads();
        float p=0.0f;
#pragma unroll
        for(int ii=0;ii<64;ii++) p=fmaf(w[ii],hs[seg+8*ii],p);
        p+=__shfl_xor_sync(~0u,p,1); p+=__shfl_xor_sync(~0u,p,2); p+=__shfl_xor_sync(~0u,p,4);
        float val=p+d_xg[(size_t)(dir*NT1+s)*G4+g*HD+j];
        float gi=__shfl_sync(~0u,val,0), gf=__shfl_sync(~0u,val,8);
        float gg=__shfl_sync(~0u,val,16),go=__shfl_sync(~0u,val,24);
        c=sigf(gf)*c+sigf(gi)*tanhf(gg);
        float h=sigf(go)*tanhf(c);
        if(l==0){
            __stcg(&d_hbuf[(dir*2+(rb^1))*HD+j],h);
            int tt=dir?(127-s):s;
            d_hcat[(size_t)tt*(2*HD)+dir*HD+j]=h;
        }
        __syncthreads();
        if(tid==0){ __threadfence(); atomicAdd((int*)bar,1);
            while(*bar<64*(s+1)){} __threadfence(); }
        __syncthreads();
    }
}

__global__ void k_us(const float* __restrict__ UW,const float* __restrict__ Ub,
                     const float* __restrict__ SW,const float* __restrict__ Sb){
    int jt=blockIdx.x, m=blockIdx.y, j0=jt*8, t=threadIdx.x;
    const float* W=m?SW:UW; const float* bb=m?Sb:Ub;
    __shared__ float Wt[8][2*HD];
    const float4* Wv=(const float4*)(W+(size_t)j0*2*HD);
    float4* Ws=(float4*)Wt;
    for(int i=t;i<8*2*HD/4;i+=128) Ws[i]=Wv[i];
    __syncthreads();
    float acc[8];
#pragma unroll
    for(int cc=0;cc<8;cc++) acc[cc]=0.0f;
    const float* hr=&d_hcat[(size_t)t*2*HD];
    for(int k=0;k<2*HD;k++){
        float hv=hr[k];
#pragma unroll
        for(int cc=0;cc<8;cc++) acc[cc]=fmaf(hv,Wt[cc][k],acc[cc]);
    }
#pragma unroll
    for(int cc=0;cc<8;cc++){
        float x=acc[cc]+bb[j0+cc];
        if(m) d_s[t*HD+j0+cc]=log1pf(expf(-fabsf(x)))+fmaxf(x,0.0f);
        else  d_u[t*HD+j0+cc]=x;
    }
}

__global__ void k_sample(){
    int r=blockIdx.x, j=threadIdx.x;
    int t = (r<128)? r : ((r-128)&127);
    u32 k0,k1; unsigned flat;
    if(r<128){ k0=d_keys[0]; k1=d_keys[1]; flat=(unsigned)(r*HD+j); }
    else     { k0=d_keys[2]; k1=d_keys[3]; flat=(unsigned)((r-128)*HD+j); }
    uint2 o=tf2x32(k0,k1,0u,flat);
    float n=jnormal(o.x^o.y);
    float uu=d_u[t*HD+j], ss=d_s[t*HD+j];
    d_z[(size_t)r*HD+j]=uu+ss*n;
    if(r<128){
        float v=0.5f*(ss*ss+uu*uu-1.0f-2.0f*logf(ss));
#pragma unroll
        for(int o2=16;o2;o2>>=1) v+=__shfl_xor_sync(~0u,v,o2);
        __shared__ float sw[16];
        if((j&31)==0) sw[j>>5]=v;
        __syncthreads();
        if(j<16){ v=sw[j];
            for(int o2=8;o2;o2>>=1) v+=__shfl_xor_sync(0xffffu,v,o2);
            if(j==0) atomicAdd(&d_kl,v);
        }
    }
}

__global__ void __launch_bounds__(256) k_logits(const float* __restrict__ fW,
        const float* __restrict__ fb,const float* __restrict__ gW,
        const float* __restrict__ gb,const int* __restrict__ wl1,
        const int* __restrict__ wl2){
    int cx=blockIdx.x, ry=blockIdx.y;
    int row0=ry*64, col0=cx*64;
    const float* W=(row0<128)?fW:gW; const float* bb=(row0<128)?fb:gb;
    int tid=threadIdx.x, tx=tid&15, ty=tid>>4, m0=ty*4, n0=tx*4;
    __shared__ float As[16][64], Bs[16][64];
    __shared__ float red[64][17];
    float acc[4][4];
#pragma unroll
    for(int i=0;i<4;i++)
#pragma unroll
        for(int q=0;q<4;q++) acc[i][q]=0.0f;
    int lm=tid&63, kq=tid>>6;
    for(int k0=0;k0<HD;k0+=16){
        float4 av=*(const float4*)&d_z[(size_t)(row0+lm)*HD+k0+kq*4];
        float4 bv=*(const float4*)&W[(size_t)(col0+lm)*HD+k0+kq*4];
        As[kq*4+0][lm]=av.x; As[kq*4+1][lm]=av.y; As[kq*4+2][lm]=av.z; As[kq*4+3][lm]=av.w;
        Bs[kq*4+0][lm]=bv.x; Bs[kq*4+1][lm]=bv.y; Bs[kq*4+2][lm]=bv.z; Bs[kq*4+3][lm]=bv.w;
        __syncthreads();
#pragma unroll
        for(int kk=0;kk<16;kk++){
            float4 a=*(const float4*)&As[kk][m0];
            float4 b=*(const float4*)&Bs[kk][n0];
            float ar[4]={a.x,a.y,a.z,a.w}, br[4]={b.x,b.y,b.z,b.w};
#pragma unroll
            for(int i=0;i<4;i++)
#pragma unroll
                for(int q=0;q<4;q++) acc[i][q]=fmaf(ar[i],br[q],acc[i][q]);
        }
        __syncthreads();
    }
#pragma unroll
    for(int q=0;q<4;q++){
        float bias=bb[col0+n0+q];
#pragma unroll
        for(int i=0;i<4;i++) acc[i][q]+=bias;
    }
#pragma unroll
    for(int i=0;i<4;i++){
        int r=row0+m0+i;
        int tw=(r<128)?wl1[r]:wl2[(r-128)>>7];
#pragma unroll
        for(int q=0;q<4;q++) if(col0+n0+q==tw) d_tgt[r]=acc[i][q];
        float mx=fmaxf(fmaxf(acc[i][0],acc[i][1]),fmaxf(acc[i][2],acc[i][3]));
        red[m0+i][tx]=mx;
    }
    __syncthreads();
    if(tid<64){ float M=red[tid][0];
#pragma unroll
        for(int q=1;q<16;q++) M=fmaxf(M,red[tid][q]);
        red[tid][16]=M;
    }
    __syncthreads();
    float se[4];
#pragma unroll
    for(int i=0;i<4;i++){
        float M=red[m0+i][16];
        se[i]=expf(acc[i][0]-M)+expf(acc[i][1]-M)+expf(acc[i][2]-M)+expf(acc[i][3]-M);
    }
    __syncthreads();
#pragma unroll
    for(int i=0;i<4;i++) red[m0+i][tx]=se[i];
    __syncthreads();
    if(tid<64){ float S=0.0f;
#pragma unroll
        for(int q=0;q<16;q++) S+=red[tid][q];
        int r=row0+tid;
        d_pm[(size_t)r*NCT+cx]=red[tid][16];
        d_ps[(size_t)r*NCT+cx]=S;
    }
}

__global__ void k_final(){
    int r=blockIdx.x, tid=threadIdx.x;
    __shared__ float sw[4]; __shared__ float sM;
    float M=-1e30f;
    for(int i=tid;i<NCT;i+=128) M=fmaxf(M,d_pm[(size_t)r*NCT+i]);
    for(int o=16;o;o>>=1) M=fmaxf(M,__shfl_xor_sync(~0u,M,o));
    if((tid&31)==0) sw[tid>>5]=M;
    __syncthreads();
    if(tid==0){ sM=fmaxf(fmaxf(sw[0],sw[1]),fmaxf(sw[2],sw[3])); }
    __syncthreads();
    float Mf=sM, S=0.0f;
    for(int i=tid;i<NCT;i+=128) S+=d_ps[(size_t)r*NCT+i]*expf(d_pm[(size_t)r*NCT+i]-Mf);
    for(int o=16;o;o>>=1) S+=__shfl_xor_sync(~0u,S,o);
    if((tid&31)==0) sw[tid>>5]=S;
    __syncthreads();
    if(tid==0){
        S=sw[0]+sw[1]+sw[2]+sw[3];
        float lp=d_tgt[r]-(logf(S)+Mf);
        float wg=(r<128)?1.0f:(1.0f/16.0f);
        atomicAdd(&d_acc,lp*wg);
    }
}

__global__ void k_out(float* out){ out[0]=-d_kl+d_acc; }

extern "C" void kernel_launch(void* const* d_in, const int* in_sizes, int n_in,
                              void* d_out, int out_size){
    const int*   wl1=(const int*)d_in[0];
    const int*   wl2=(const int*)d_in[1];
    const float* emb=(const float*)d_in[2];
    const float* Wihf=(const float*)d_in[3];
    const float* Whhf=(const float*)d_in[4];
    const float* bihf=(const float*)d_in[5];
    const float* bhhf=(const float*)d_in[6];
    const float* Wihb=(const float*)d_in[7];
    const float* Whhb=(const float*)d_in[8];
    const float* bihb=(const float*)d_in[9];
    const float* bhhb=(const float*)d_in[10];
    const float* UW=(const float*)d_in[11];
    const float* Ub=(const float*)d_in[12];
    const float* SW=(const float*)d_in[13];
    const float* Sb=(const float*)d_in[14];
    const float* fW=(const float*)d_in[15];
    const float* fb=(const float*)d_in[16];
    const float* gW=(const float*)d_in[17];
    const float* gb=(const float*)d_in[18];
    k_init<<<256,128>>>(wl1,emb);
    k_xg<<<dim3(128,2),128>>>(Wihf,bihf,bhhf,Wihb,bihb,bhhb);
    k_lstm<<<128,256>>>(Whhf,Whhb);
    k_us<<<dim3(64,2),128>>>(UW,Ub,SW,Sb);
    k_sample<<<RTOT,512>>>();
    k_logits<<<dim3(NCT,34),256>>>(fW,fb,gW,gb,wl1,wl2);
    k_final<<<RTOT,128>>>();
    k_out<<<1,1>>>((float*)d_out);
}

// round 5
// speedup vs baseline: 3.6673x; 3.6673x over previous
#include <cuda_runtime.h>
#include <cuda_bf16.h>
typedef unsigned int u32; typedef unsigned long long u64;

#define NT1 128
#define ED  256
#define HD  512
#define G4  2048
#define RTOT 2176
#define NCT 250
#define VV  32000

__device__ float d_xT[ED*NT1];
__device__ float d_xg[2*NT1*G4];
__device__ float d_hbuf[2*2*HD];
__device__ float d_hcat[NT1*2*HD];
__device__ float d_u[NT1*HD];
__device__ float d_s[NT1*HD];
__device__ __align__(16) __nv_bfloat16 d_zb[(size_t)RTOT*HD];
__device__ __align__(16) __nv_bfloat16 d_fWb[(size_t)VV*HD];
__device__ __align__(16) __nv_bfloat16 d_gWb[(size_t)VV*HD];
__device__ float d_pm[(size_t)RTOT*NCT];
__device__ float d_ps[(size_t)RTOT*NCT];
__device__ float d_tgt[RTOT];
__device__ u32 d_keys[4];
__device__ int d_barc[2];
__device__ float d_kl, d_acc;

__device__ __forceinline__ uint2 tf2x32(u32 k0,u32 k1,u32 c0,u32 c1){
    u32 ks2=0x1BD11BDAu^k0^k1, x0=c0+k0, x1=c1+k1;
#define TFR(r) {x0+=x1; x1=__funnelshift_l(x1,x1,r); x1^=x0;}
    TFR(13)TFR(15)TFR(26)TFR(6)  x0+=k1;  x1+=ks2+1u;
    TFR(17)TFR(29)TFR(16)TFR(24) x0+=ks2; x1+=k0+2u;
    TFR(13)TFR(15)TFR(26)TFR(6)  x0+=k0;  x1+=k1+3u;
    TFR(17)TFR(29)TFR(16)TFR(24) x0+=k1;  x1+=ks2+4u;
    TFR(13)TFR(15)TFR(26)TFR(6)  x0+=ks2; x1+=k0+5u;
#undef TFR
    return make_uint2(x0,x1);
}
__device__ __forceinline__ float jnormal(u32 bits){
    float f=__uint_as_float((bits>>9)|0x3f800000u)-1.0f;
    const float lo=__int_as_float(0xBF7FFFFF);
    float u=fmaxf(lo, f*(1.0f-lo)+lo);
    float w=-log1pf(-u*u), p;
    if(w<5.0f){ w-=2.5f;
        p=2.81022636e-08f;           p=fmaf(p,w,3.43273939e-07f);
        p=fmaf(p,w,-3.5233877e-06f); p=fmaf(p,w,-4.39150654e-06f);
        p=fmaf(p,w,0.00021858087f);  p=fmaf(p,w,-0.00125372503f);
        p=fmaf(p,w,-0.00417768164f); p=fmaf(p,w,0.246640727f);
        p=fmaf(p,w,1.50140941f);
    } else { w=sqrtf(w)-3.0f;
        p=-0.000200214257f;          p=fmaf(p,w,0.000100950558f);
        p=fmaf(p,w,0.00134934322f);  p=fmaf(p,w,-0.00367342844f);
        p=fmaf(p,w,0.00573950773f);  p=fmaf(p,w,-0.0076224613f);
        p=fmaf(p,w,0.00943887047f);  p=fmaf(p,w,1.00167406f);
        p=fmaf(p,w,2.83297682f);
    }
    return 1.41421354f*(p*u);
}
__device__ __forceinline__ float sigf(float x){ return 1.0f/(1.0f+expf(-x)); }

__global__ void k_init(const int* __restrict__ wl1, const float* __restrict__ emb){
    int tid=blockIdx.x*blockDim.x+threadIdx.x;
    int t=tid&127, k=tid>>7;
    d_xT[k*NT1+t]=emb[(size_t)wl1[t]*ED+k];
    if(tid<2048) d_hbuf[tid]=0.0f;
    if(tid<2) d_barc[tid]=0;
    if(tid==0){
        d_kl=0.0f; d_acc=0.0f;
        uint2 a=tf2x32(0u,42u,0u,0u), b=tf2x32(0u,42u,0u,1u);
        d_keys[0]=a.x; d_keys[1]=a.y; d_keys[2]=b.x; d_keys[3]=b.y;
    }
}

__global__ void k_cvt(const float* __restrict__ fW,const float* __restrict__ gW){
    size_t i=((size_t)blockIdx.x*blockDim.x+threadIdx.x)*4;
    float4 a=*(const float4*)(fW+i);
    __nv_bfloat162* o=(__nv_bfloat162*)(d_fWb+i);
    o[0]=__floats2bfloat162_rn(a.x,a.y); o[1]=__floats2bfloat162_rn(a.z,a.w);
    float4 b=*(const float4*)(gW+i);
    __nv_bfloat162* o2=(__nv_bfloat162*)(d_gWb+i);
    o2[0]=__floats2bfloat162_rn(b.x,b.y); o2[1]=__floats2bfloat162_rn(b.z,b.w);
}

__global__ void k_xg(const float* __restrict__ Wf,const float* __restrict__ bif,
                     const float* __restrict__ bhf,const float* __restrict__ Wb,
                     const float* __restrict__ bib,const float* __restrict__ bhb){
    int dir=blockIdx.y, j0=blockIdx.x*16, t=threadIdx.x;
    const float* W = dir?Wb:Wf; const float* b1=dir?bib:bif; const float* b2=dir?bhb:bhf;
    __shared__ float Ws[16][ED]; __shared__ float bs[16];
    for(int i=t;i<16*ED;i+=128) Ws[i>>8][i&255]=W[(size_t)(j0+(i>>8))*ED+(i&255)];
    if(t<16) bs[t]=b1[j0+t]+b2[j0+t];
    __syncthreads();
    int ts = dir?(127-t):t;
    float acc[16];
#pragma unroll
    for(int c=0;c<16;c++) acc[c]=0.0f;
    for(int k=0;k<ED;k++){
        float xv=d_xT[k*NT1+ts];
#pragma unroll
        for(int c=0;c<16;c++) acc[c]=fmaf(xv,Ws[c][k],acc[c]);
    }
#pragma unroll
    for(int c=0;c<16;c++) d_xg[(size_t)(dir*NT1+t)*G4+j0+c]=acc[c]+bs[c];
}

__global__ void __launch_bounds__(256,1) k_lstm(const float* __restrict__ Whf,
                                                const float* __restrict__ Whb){
    int bid=blockIdx.x, dir=bid>>6, blk=bid&63, j0=blk*8;
    int tid=threadIdx.x, wp=tid>>5, l=tid&31, g=l>>3, seg=l&7;
    int j=j0+wp;
    const float* Whh = dir?Whb:Whf;
    float w[64];
    {
        const float* wr=Whh+(size_t)(g*HD+j)*HD+seg;
#pragma unroll
        for(int ii=0;ii<64;ii++) w[ii]=wr[ii*8];
    }
    __shared__ float hs[HD];
    float c=0.0f;
    volatile int* bar=&d_barc[dir];
    for(int s=0;s<NT1;s++){
        int rb=s&1, base=(dir*2+rb)*HD;
        hs[tid]    =__ldcg(&d_hbuf[base+tid]);
        hs[tid+256]=__ldcg(&d_hbuf[base+tid+256]);
        __syncthreads();
        float p=0.0f;
#pragma unroll
        for(int ii=0;ii<64;ii++) p=fmaf(w[ii],hs[seg+8*ii],p);
        p+=__shfl_xor_sync(~0u,p,1); p+=__shfl_xor_sync(~0u,p,2); p+=__shfl_xor_sync(~0u,p,4);
        float val=p+d_xg[(size_t)(dir*NT1+s)*G4+g*HD+j];
        float gi=__shfl_sync(~0u,val,0), gf=__shfl_sync(~0u,val,8);
        float gg=__shfl_sync(~0u,val,16),go=__shfl_sync(~0u,val,24);
        c=sigf(gf)*c+sigf(gi)*tanhf(gg);
        float h=sigf(go)*tanhf(c);
        if(l==0){
            __stcg(&d_hbuf[(dir*2+(rb^1))*HD+j],h);
            int tt=dir?(127-s):s;
            d_hcat[(size_t)tt*(2*HD)+dir*HD+j]=h;
        }
        __syncthreads();
        if(tid==0){ __threadfence(); atomicAdd((int*)bar,1);
            while(*bar<64*(s+1)){} __threadfence(); }
        __syncthreads();
    }
}

__global__ void k_us(const float* __restrict__ UW,const float* __restrict__ Ub,
                     const float* __restrict__ SW,const float* __restrict__ Sb){
    int jt=blockIdx.x, m=blockIdx.y, j0=jt*8, t=threadIdx.x;
    const float* W=m?SW:UW; const float* bb=m?Sb:Ub;
    __shared__ float Wt[8][2*HD];
    const float4* Wv=(const float4*)(W+(size_t)j0*2*HD);
    float4* Ws=(float4*)Wt;
    for(int i=t;i<8*2*HD/4;i+=128) Ws[i]=Wv[i];
    __syncthreads();
    float acc[8];
#pragma unroll
    for(int cc=0;cc<8;cc++) acc[cc]=0.0f;
    const float4* h4=(const float4*)&d_hcat[(size_t)t*2*HD];
    for(int k=0;k<2*HD/4;k++){
        float4 hv=h4[k];
#pragma unroll
        for(int cc=0;cc<8;cc++){
            float4 wv=*(const float4*)&Wt[cc][k*4];
            acc[cc]=fmaf(hv.x,wv.x,fmaf(hv.y,wv.y,fmaf(hv.z,wv.z,fmaf(hv.w,wv.w,acc[cc]))));
        }
    }
#pragma unroll
    for(int cc=0;cc<8;cc++){
        float x=acc[cc]+bb[j0+cc];
        if(m) d_s[t*HD+j0+cc]=log1pf(expf(-fabsf(x)))+fmaxf(x,0.0f);
        else  d_u[t*HD+j0+cc]=x;
    }
}

__global__ void k_sample(){
    int r=blockIdx.x, j=threadIdx.x;
    int t = (r<128)? r : ((r-128)&127);
    u32 k0,k1; unsigned flat;
    if(r<128){ k0=d_keys[0]; k1=d_keys[1]; flat=(unsigned)(r*HD+j); }
    else     { k0=d_keys[2]; k1=d_keys[3]; flat=(unsigned)((r-128)*HD+j); }
    uint2 o=tf2x32(k0,k1,0u,flat);
    float n=jnormal(o.x^o.y);
    float uu=d_u[t*HD+j], ss=d_s[t*HD+j];
    d_zb[(size_t)r*HD+j]=__float2bfloat16_rn(uu+ss*n);
    if(r<128){
        float v=0.5f*(ss*ss+uu*uu-1.0f-2.0f*logf(ss));
#pragma unroll
        for(int o2=16;o2;o2>>=1) v+=__shfl_xor_sync(~0u,v,o2);
        __shared__ float sw[16];
        if((j&31)==0) sw[j>>5]=v;
        __syncthreads();
        if(j<16){ v=sw[j];
            for(int o2=8;o2;o2>>=1) v+=__shfl_xor_sync(0xffffu,v,o2);
            if(j==0) atomicAdd(&d_kl,v);
        }
    }
}

// bf16 mma.sync GEMM (128x128 tile, K=512) fused with bias + online log-softmax partials.
__global__ void __launch_bounds__(256) k_mma(const float* __restrict__ fb,const float* __restrict__ gb,
        const int* __restrict__ wl1,const int* __restrict__ wl2){
    __shared__ __align__(16) __nv_bfloat16 As[128*72];
    __shared__ __align__(16) __nv_bfloat16 Bs[128*72];
    __shared__ float sbias[128];
    __shared__ float red_m[128][4];
    __shared__ float red_s[128][4];
    int tid=threadIdx.x, cx=blockIdx.x, ry=blockIdx.y;
    int col0=cx*128, row0=ry*128;
    const __nv_bfloat16* Wsrc = ry? d_gWb : d_fWb;
    const float* bb = ry? gb : fb;
    if(tid<128) sbias[tid]=bb[col0+tid];
    int lane=tid&31, warp=tid>>5, rw=warp>>2, cw=warp&3;
    float acc[4][4][4];
#pragma unroll
    for(int mt=0;mt<4;mt++)
#pragma unroll
        for(int nt=0;nt<4;nt++)
#pragma unroll
            for(int q=0;q<4;q++) acc[mt][nt][q]=0.0f;
    int lr=tid>>1, half=(tid&1);
    const uint4* gA=(const uint4*)(d_zb+(size_t)(row0+lr)*HD);
    const uint4* gB=(const uint4*)(Wsrc+(size_t)(col0+lr)*HD);
    const __nv_bfloat16* Ab=As+(size_t)(rw*64+(lane>>2))*72;
    const __nv_bfloat16* Bb=Bs+(size_t)(cw*32+(lane>>2))*72;
    for(int ch=0;ch<8;ch++){
#pragma unroll
        for(int i=0;i<4;i++){
            uint4 v=gA[ch*8+half*4+i];
            *(uint4*)(As+(size_t)lr*72+half*32+i*8)=v;
            uint4 w2=gB[ch*8+half*4+i];
            *(uint4*)(Bs+(size_t)lr*72+half*32+i*8)=w2;
        }
        __syncthreads();
#pragma unroll
        for(int ks=0;ks<4;ks++){
            int kc=ks*16+(lane&3)*2;
            u32 a[4][4], b2[4][2];
#pragma unroll
            for(int mt=0;mt<4;mt++){
                a[mt][0]=*(const u32*)(Ab+mt*16*72+kc);
                a[mt][1]=*(const u32*)(Ab+(mt*16+8)*72+kc);
                a[mt][2]=*(const u32*)(Ab+mt*16*72+kc+8);
                a[mt][3]=*(const u32*)(Ab+(mt*16+8)*72+kc+8);
            }
#pragma unroll
            for(int nt=0;nt<4;nt++){
                b2[nt][0]=*(const u32*)(Bb+nt*8*72+kc);
                b2[nt][1]=*(const u32*)(Bb+nt*8*72+kc+8);
            }
#pragma unroll
            for(int mt=0;mt<4;mt++)
#pragma unroll
                for(int nt=0;nt<4;nt++)
                    asm volatile("mma.sync.aligned.m16n8k16.row.col.f32.bf16.bf16.f32 "
                        "{%0,%1,%2,%3},{%4,%5,%6,%7},{%8,%9},{%0,%1,%2,%3};"
                        :"+f"(acc[mt][nt][0]),"+f"(acc[mt][nt][1]),"+f"(acc[mt][nt][2]),"+f"(acc[mt][nt][3])
                        :"r"(a[mt][0]),"r"(a[mt][1]),"r"(a[mt][2]),"r"(a[mt][3]),
                         "r"(b2[nt][0]),"r"(b2[nt][1]));
        }
        __syncthreads();
    }
    // fold bias
#pragma unroll
    for(int mt=0;mt<4;mt++)
#pragma unroll
        for(int nt=0;nt<4;nt++){
            float b0=sbias[cw*32+nt*8+(lane&3)*2], b1=sbias[cw*32+nt*8+(lane&3)*2+1];
            acc[mt][nt][0]+=b0; acc[mt][nt][1]+=b1;
            acc[mt][nt][2]+=b0; acc[mt][nt][3]+=b1;
        }
    // pass1: per-row max
#pragma unroll
    for(int mt=0;mt<4;mt++)
#pragma unroll
        for(int h=0;h<2;h++){
            float m=-1e30f;
#pragma unroll
            for(int nt=0;nt<4;nt++) m=fmaxf(m,fmaxf(acc[mt][nt][h*2],acc[mt][nt][h*2+1]));
            m=fmaxf(m,__shfl_xor_sync(~0u,m,1));
            m=fmaxf(m,__shfl_xor_sync(~0u,m,2));
            if((lane&3)==0) red_m[rw*64+mt*16+(lane>>2)+h*8][cw]=m;
        }
    __syncthreads();
    // pass2: sum-exp with global row max + target gather
#pragma unroll
    for(int mt=0;mt<4;mt++)
#pragma unroll
        for(int h=0;h<2;h++){
            int rloc=rw*64+mt*16+(lane>>2)+h*8;
            int rg=row0+rloc;
            float M=fmaxf(fmaxf(red_m[rloc][0],red_m[rloc][1]),fmaxf(red_m[rloc][2],red_m[rloc][3]));
            int tw=(rg<128)?wl1[rg]:wl2[(rg-128)>>7];
            int tloc=tw-col0;
            float s=0.0f;
#pragma unroll
            for(int nt=0;nt<4;nt++){
                int c0=cw*32+nt*8+(lane&3)*2;
                float v0=acc[mt][nt][h*2], v1=acc[mt][nt][h*2+1];
                if(c0==tloc)   d_tgt[rg]=v0;
                if(c0+1==tloc) d_tgt[rg]=v1;
                s+=__expf(v0-M)+__expf(v1-M);
            }
            s+=__shfl_xor_sync(~0u,s,1);
            s+=__shfl_xor_sync(~0u,s,2);
            if((lane&3)==0) red_s[rloc][cw]=s;
        }
    __syncthreads();
    if(tid<128){
        float M=fmaxf(fmaxf(red_m[tid][0],red_m[tid][1]),fmaxf(red_m[tid][2],red_m[tid][3]));
        float S=red_s[tid][0]+red_s[tid][1]+red_s[tid][2]+red_s[tid][3];
        int rg=row0+tid;
        d_pm[(size_t)rg*NCT+cx]=M;
        d_ps[(size_t)rg*NCT+cx]=S;
    }
}

__global__ void k_final(){
    int r=blockIdx.x, tid=threadIdx.x;
    __shared__ float sw[4]; __shared__ float sM;
    float M=-1e30f;
    for(int i=tid;i<NCT;i+=128) M=fmaxf(M,d_pm[(size_t)r*NCT+i]);
    for(int o=16;o;o>>=1) M=fmaxf(M,__shfl_xor_sync(~0u,M,o));
    if((tid&31)==0) sw[tid>>5]=M;
    __syncthreads();
    if(tid==0) sM=fmaxf(fmaxf(sw[0],sw[1]),fmaxf(sw[2],sw[3]));
    __syncthreads();
    float Mf=sM, S=0.0f;
    for(int i=tid;i<NCT;i+=128) S+=d_ps[(size_t)r*NCT+i]*expf(d_pm[(size_t)r*NCT+i]-Mf);
    for(int o=16;o;o>>=1) S+=__shfl_xor_sync(~0u,S,o);
    if((tid&31)==0) sw[tid>>5]=S;
    __syncthreads();
    if(tid==0){
        S=sw[0]+sw[1]+sw[2]+sw[3];
        float lp=d_tgt[r]-(logf(S)+Mf);
        float wg=(r<128)?1.0f:(1.0f/16.0f);
        atomicAdd(&d_acc,lp*wg);
    }
}

__global__ void k_out(float* out){ out[0]=-d_kl+d_acc; }

extern "C" void kernel_launch(void* const* d_in, const int* in_sizes, int n_in,
                              void* d_out, int out_size){
    const int*   wl1=(const int*)d_in[0];
    const int*   wl2=(const int*)d_in[1];
    const float* emb=(const float*)d_in[2];
    const float* Wihf=(const float*)d_in[3];
    const float* Whhf=(const float*)d_in[4];
    const float* bihf=(const float*)d_in[5];
    const float* bhhf=(const float*)d_in[6];
    const float* Wihb=(const float*)d_in[7];
    const float* Whhb=(const float*)d_in[8];
    const float* bihb=(const float*)d_in[9];
    const float* bhhb=(const float*)d_in[10];
    const float* UW=(const float*)d_in[11];
    const float* Ub=(const float*)d_in[12];
    const float* SW=(const float*)d_in[13];
    const float* Sb=(const float*)d_in[14];
    const float* fW=(const float*)d_in[15];
    const float* fb=(const float*)d_in[16];
    const float* gW=(const float*)d_in[17];
    const float* gb=(const float*)d_in[18];
    k_init<<<256,128>>>(wl1,emb);
    k_cvt<<<16000,256>>>(fW,gW);
    k_xg<<<dim3(128,2),128>>>(Wihf,bihf,bhhf,Wihb,bihb,bhhb);
    k_lstm<<<128,256>>>(Whhf,Whhb);
    k_us<<<dim3(64,2),128>>>(UW,Ub,SW,Sb);
    k_sample<<<RTOT,512>>>();
    k_mma<<<dim3(NCT,17),256>>>(fb,gb,wl1,wl2);
    k_final<<<RTOT,128>>>();
    k_out<<<1,1>>>((float*)d_out);
}